// round 1
// baseline (speedup 1.0000x reference)
#include <cuda_runtime.h>
#include <cuda_bf16.h>
#include <math.h>

// Problem constants
#define BATCH     4
#define SEQ       2048
#define DMODEL    1024
#define NHEAD     16
#define HDIM      64
#define MROWS     (BATCH * SEQ)          // 8192
#define SCALE_QK  0.125f                 // 1/sqrt(64)

// ---------------------------------------------------------------------------
// Scratch buffers (device globals: allocation-free per harness rules)
// ---------------------------------------------------------------------------
__device__ float g_Q[MROWS * DMODEL];
__device__ float g_K[MROWS * DMODEL];
__device__ float g_V[MROWS * DMODEL];
__device__ float g_CTX[MROWS * DMODEL];

// ---------------------------------------------------------------------------
// GEMM: C[M, 1024] = A[M, 1024] * W[1024, 1024]^T + bias
// (torch Linear convention: out[m,n] = sum_k A[m,k] * W[n,k] + b[n])
// Block tile 128x128, BK=8, 256 threads, 8x8 register tile per thread.
// ---------------------------------------------------------------------------
__global__ void __launch_bounds__(256)
gemm_nt_bias(const float* __restrict__ A,
             const float* __restrict__ W,
             const float* __restrict__ bias,
             float* __restrict__ C)
{
    __shared__ float As[8][128];   // [k][m]
    __shared__ float Bs[8][128];   // [k][n]

    const int tid = threadIdx.x;
    const int tx  = tid & 15;      // 0..15  (n direction)
    const int ty  = tid >> 4;      // 0..15  (m direction)

    const int bm = blockIdx.y * 128;
    const int bn = blockIdx.x * 128;

    // loader mapping: 256 threads cover 128 rows x 8 k, one float4 each
    const int lrow = tid >> 1;            // 0..127
    const int lk   = (tid & 1) * 4;       // 0 or 4

    const float* Aptr = A + (size_t)(bm + lrow) * DMODEL + lk;
    const float* Wptr = W + (size_t)(bn + lrow) * DMODEL + lk;

    float acc[8][8];
#pragma unroll
    for (int i = 0; i < 8; i++)
#pragma unroll
        for (int j = 0; j < 8; j++) acc[i][j] = 0.0f;

    // software pipeline: prefetch k0=0
    float4 av = *(const float4*)(Aptr);
    float4 wv = *(const float4*)(Wptr);

    for (int k0 = 0; k0 < DMODEL; k0 += 8) {
        __syncthreads();
        // store (transposed) into smem
        As[lk + 0][lrow] = av.x; As[lk + 1][lrow] = av.y;
        As[lk + 2][lrow] = av.z; As[lk + 3][lrow] = av.w;
        Bs[lk + 0][lrow] = wv.x; Bs[lk + 1][lrow] = wv.y;
        Bs[lk + 2][lrow] = wv.z; Bs[lk + 3][lrow] = wv.w;
        __syncthreads();

        // prefetch next k-slab while computing this one
        if (k0 + 8 < DMODEL) {
            av = *(const float4*)(Aptr + k0 + 8);
            wv = *(const float4*)(Wptr + k0 + 8);
        }

#pragma unroll
        for (int kk = 0; kk < 8; kk++) {
            float4 a0 = *(const float4*)&As[kk][ty * 8];
            float4 a1 = *(const float4*)&As[kk][ty * 8 + 4];
            float4 b0 = *(const float4*)&Bs[kk][tx * 8];
            float4 b1 = *(const float4*)&Bs[kk][tx * 8 + 4];
            float a[8] = {a0.x, a0.y, a0.z, a0.w, a1.x, a1.y, a1.z, a1.w};
            float b[8] = {b0.x, b0.y, b0.z, b0.w, b1.x, b1.y, b1.z, b1.w};
#pragma unroll
            for (int i = 0; i < 8; i++)
#pragma unroll
                for (int j = 0; j < 8; j++)
                    acc[i][j] = fmaf(a[i], b[j], acc[i][j]);
        }
    }

    // epilogue with bias, vectorized stores
#pragma unroll
    for (int i = 0; i < 8; i++) {
        const int row = bm + ty * 8 + i;
        float* crow = C + (size_t)row * DMODEL + bn + tx * 8;
        const float* brow = bias + bn + tx * 8;
        float4 o0, o1;
        o0.x = acc[i][0] + brow[0]; o0.y = acc[i][1] + brow[1];
        o0.z = acc[i][2] + brow[2]; o0.w = acc[i][3] + brow[3];
        o1.x = acc[i][4] + brow[4]; o1.y = acc[i][5] + brow[5];
        o1.z = acc[i][6] + brow[6]; o1.w = acc[i][7] + brow[7];
        *(float4*)(crow)     = o0;
        *(float4*)(crow + 4) = o1;
    }
}

// ---------------------------------------------------------------------------
// Causal flash attention, fp32.
// Grid: (SEQ/64, BATCH*NHEAD). Block: 256 threads.
// Each block: 64 query rows for one (b,h); iterates causal key tiles of 64.
// Thread (tx,ty): scores frag = rows ty*4..+3 x keys tx*4..+3,
//                 output frag = rows ty*4..+3 x dims tx*4..+3.
// ---------------------------------------------------------------------------
#define FA_PAD 68   // 68 floats per row -> 272B (16B aligned), conflict padding

__global__ void __launch_bounds__(256)
flash_attn(const float* __restrict__ Qg,
           const float* __restrict__ Kg,
           const float* __restrict__ Vg,
           float* __restrict__ Og)
{
    extern __shared__ float sm[];
    float (*Qs)[FA_PAD] = (float(*)[FA_PAD])(sm);                 // [d][q]
    float (*Ks)[FA_PAD] = (float(*)[FA_PAD])(sm + 64 * FA_PAD);   // [d][k]
    float (*Vs)[FA_PAD] = (float(*)[FA_PAD])(sm + 2 * 64 * FA_PAD); // [k][d]
    float (*Ps)[FA_PAD] = (float(*)[FA_PAD])(sm + 3 * 64 * FA_PAD); // [k][q]

    const int tid = threadIdx.x;
    const int tx  = tid & 15;
    const int ty  = tid >> 4;

    const int qi = blockIdx.x;           // query tile index (0..31)
    const int bh = blockIdx.y;           // 0..63
    const int b  = bh >> 4;
    const int h  = bh & 15;

    const size_t headoff = (size_t)b * SEQ * DMODEL + (size_t)h * HDIM;
    const float* Qbase = Qg + headoff;
    const float* Kbase = Kg + headoff;
    const float* Vbase = Vg + headoff;

    const int qb = qi * 64;

    // ---- load Q tile (transposed) ----
    {
        const int lr = tid >> 4;          // 0..15
        const int lc = (tid & 15) * 4;    // 0..60
#pragma unroll
        for (int r = 0; r < 4; r++) {
            const int row = lr + r * 16;
            float4 v = *(const float4*)(Qbase + (size_t)(qb + row) * DMODEL + lc);
            Qs[lc + 0][row] = v.x; Qs[lc + 1][row] = v.y;
            Qs[lc + 2][row] = v.z; Qs[lc + 3][row] = v.w;
        }
    }

    float o[4][4];
    float m_run[4], l_run[4];
#pragma unroll
    for (int i = 0; i < 4; i++) {
        m_run[i] = -1e30f;
        l_run[i] = 0.0f;
#pragma unroll
        for (int j = 0; j < 4; j++) o[i][j] = 0.0f;
    }

    for (int kt = 0; kt <= qi; kt++) {
        __syncthreads();   // prior-iter reads of Ks/Vs/Ps complete
        // ---- load K (transposed) + V (direct) tiles ----
        {
            const int lr = tid >> 4;
            const int lc = (tid & 15) * 4;
#pragma unroll
            for (int r = 0; r < 4; r++) {
                const int row = lr + r * 16;
                const size_t goff = (size_t)(kt * 64 + row) * DMODEL + lc;
                float4 kv = *(const float4*)(Kbase + goff);
                Ks[lc + 0][row] = kv.x; Ks[lc + 1][row] = kv.y;
                Ks[lc + 2][row] = kv.z; Ks[lc + 3][row] = kv.w;
                float4 vv = *(const float4*)(Vbase + goff);
                *(float4*)&Vs[row][lc] = vv;
            }
        }
        __syncthreads();

        // ---- scores S = (Q Kt) * scale ----
        float s[4][4];
#pragma unroll
        for (int i = 0; i < 4; i++)
#pragma unroll
            for (int j = 0; j < 4; j++) s[i][j] = 0.0f;

#pragma unroll 8
        for (int d = 0; d < 64; d++) {
            float4 aq = *(const float4*)&Qs[d][ty * 4];
            float4 bk = *(const float4*)&Ks[d][tx * 4];
            float a[4] = {aq.x, aq.y, aq.z, aq.w};
            float bb[4] = {bk.x, bk.y, bk.z, bk.w};
#pragma unroll
            for (int i = 0; i < 4; i++)
#pragma unroll
                for (int j = 0; j < 4; j++)
                    s[i][j] = fmaf(a[i], bb[j], s[i][j]);
        }

        const bool diag = (kt == qi);
#pragma unroll
        for (int i = 0; i < 4; i++) {
            const int qrow = qb + ty * 4 + i;
#pragma unroll
            for (int j = 0; j < 4; j++) {
                s[i][j] *= SCALE_QK;
                if (diag) {
                    const int kcol = kt * 64 + tx * 4 + j;
                    if (kcol > qrow) s[i][j] = -1e30f;
                }
            }
        }

        // ---- online softmax update (row reductions across 16 tx lanes) ----
#pragma unroll
        for (int i = 0; i < 4; i++) {
            float rm = fmaxf(fmaxf(s[i][0], s[i][1]), fmaxf(s[i][2], s[i][3]));
#pragma unroll
            for (int off = 8; off > 0; off >>= 1)
                rm = fmaxf(rm, __shfl_xor_sync(0xffffffffu, rm, off));

            const float mnew  = fmaxf(m_run[i], rm);
            const float alpha = __expf(m_run[i] - mnew);

            float p0 = __expf(s[i][0] - mnew);
            float p1 = __expf(s[i][1] - mnew);
            float p2 = __expf(s[i][2] - mnew);
            float p3 = __expf(s[i][3] - mnew);

            float rs = p0 + p1 + p2 + p3;
#pragma unroll
            for (int off = 8; off > 0; off >>= 1)
                rs += __shfl_xor_sync(0xffffffffu, rs, off);

            l_run[i] = l_run[i] * alpha + rs;
            m_run[i] = mnew;
#pragma unroll
            for (int j = 0; j < 4; j++) o[i][j] *= alpha;

            // store P transposed: Ps[k][q]
            const int qloc = ty * 4 + i;
            Ps[tx * 4 + 0][qloc] = p0;
            Ps[tx * 4 + 1][qloc] = p1;
            Ps[tx * 4 + 2][qloc] = p2;
            Ps[tx * 4 + 3][qloc] = p3;
        }
        __syncthreads();

        // ---- O += P @ V ----
#pragma unroll 8
        for (int kk = 0; kk < 64; kk++) {
            float4 ap = *(const float4*)&Ps[kk][ty * 4];
            float4 bv = *(const float4*)&Vs[kk][tx * 4];
            float a[4] = {ap.x, ap.y, ap.z, ap.w};
            float bb[4] = {bv.x, bv.y, bv.z, bv.w};
#pragma unroll
            for (int i = 0; i < 4; i++)
#pragma unroll
                for (int j = 0; j < 4; j++)
                    o[i][j] = fmaf(a[i], bb[j], o[i][j]);
        }
    }

    // ---- epilogue: normalize and write context ----
#pragma unroll
    for (int i = 0; i < 4; i++) {
        const float inv = 1.0f / l_run[i];
        const int qrow = qb + ty * 4 + i;
        float* orow = Og + (size_t)b * SEQ * DMODEL + (size_t)qrow * DMODEL
                    + (size_t)h * HDIM + tx * 4;
        float4 ov;
        ov.x = o[i][0] * inv; ov.y = o[i][1] * inv;
        ov.z = o[i][2] * inv; ov.w = o[i][3] * inv;
        *(float4*)orow = ov;
    }
}

// ---------------------------------------------------------------------------
// Launch
// ---------------------------------------------------------------------------
extern "C" void kernel_launch(void* const* d_in, const int* in_sizes, int n_in,
                              void* d_out, int out_size)
{
    (void)in_sizes; (void)n_in; (void)out_size;
    const float* query = (const float*)d_in[0];
    const float* key   = (const float*)d_in[1];
    const float* value = (const float*)d_in[2];
    // d_in[3] = mask (tril) — causal is hardcoded in flash_attn
    const float* wq = (const float*)d_in[4];
    const float* bq = (const float*)d_in[5];
    const float* wk = (const float*)d_in[6];
    const float* bk = (const float*)d_in[7];
    const float* wv = (const float*)d_in[8];
    const float* bv = (const float*)d_in[9];
    const float* wo = (const float*)d_in[10];
    const float* bo = (const float*)d_in[11];
    float* out = (float*)d_out;

    float *gQ, *gK, *gV, *gC;
    cudaGetSymbolAddress((void**)&gQ, g_Q);
    cudaGetSymbolAddress((void**)&gK, g_K);
    cudaGetSymbolAddress((void**)&gV, g_V);
    cudaGetSymbolAddress((void**)&gC, g_CTX);

    const dim3 ggrid(DMODEL / 128, MROWS / 128);   // (8, 64)
    gemm_nt_bias<<<ggrid, 256>>>(query, wq, bq, gQ);
    gemm_nt_bias<<<ggrid, 256>>>(key,   wk, bk, gK);
    gemm_nt_bias<<<ggrid, 256>>>(value, wv, bv, gV);

    const int fa_smem = 4 * 64 * FA_PAD * (int)sizeof(float);  // 69632 B
    cudaFuncSetAttribute(flash_attn,
                         cudaFuncAttributeMaxDynamicSharedMemorySize, fa_smem);
    flash_attn<<<dim3(SEQ / 64, BATCH * NHEAD), 256, fa_smem>>>(gQ, gK, gV, gC);

    gemm_nt_bias<<<ggrid, 256>>>(gC, wo, bo, out);
}

// round 5
// speedup vs baseline: 1.4793x; 1.4793x over previous
#include <cuda_runtime.h>
#include <cuda_bf16.h>
#include <math.h>
#include <stdint.h>

// Problem constants
#define BATCH     4
#define SEQ       2048
#define DMODEL    1024
#define NHEAD     16
#define HDIM      64
#define MROWS     (BATCH * SEQ)          // 8192
#define SCALE_QK  0.125f                 // 1/sqrt(64)

// ---------------------------------------------------------------------------
// Scratch buffers (device globals: allocation-free per harness rules)
// ---------------------------------------------------------------------------
__device__ float g_Q[MROWS * DMODEL];
__device__ float g_K[MROWS * DMODEL];
__device__ float g_V[MROWS * DMODEL];
__device__ float g_CTX[MROWS * DMODEL];
__device__ __nv_bfloat16 g_Ahi[MROWS * DMODEL];
__device__ __nv_bfloat16 g_Alo[MROWS * DMODEL];
__device__ __nv_bfloat16 g_Whi[DMODEL * DMODEL];
__device__ __nv_bfloat16 g_Wlo[DMODEL * DMODEL];

// ---------------------------------------------------------------------------
// sm_80-level primitives (safe on sm_100 base target)
// ---------------------------------------------------------------------------
__device__ __forceinline__ uint32_t smem_u32(const void* p) {
    uint32_t a;
    asm("{ .reg .u64 t; cvta.to.shared.u64 t, %1; cvt.u32.u64 %0, t; }"
        : "=r"(a) : "l"(p));
    return a;
}

#define CP_ASYNC16(dst, src) \
    asm volatile("cp.async.cg.shared.global [%0], [%1], 16;" \
                 :: "r"(dst), "l"(src) : "memory")
#define CP_COMMIT() asm volatile("cp.async.commit_group;" ::: "memory")
#define CP_WAIT(n)  asm volatile("cp.async.wait_group %0;" :: "n"(n) : "memory")

__device__ __forceinline__ void ldsm_x4(uint32_t& r0, uint32_t& r1,
                                        uint32_t& r2, uint32_t& r3,
                                        uint32_t addr) {
    asm volatile("ldmatrix.sync.aligned.m8n8.x4.shared.b16 {%0,%1,%2,%3}, [%4];"
                 : "=r"(r0), "=r"(r1), "=r"(r2), "=r"(r3) : "r"(addr));
}

__device__ __forceinline__ void mma_bf16(float* d, const uint32_t* a,
                                         const uint32_t* b) {
    asm volatile(
        "mma.sync.aligned.m16n8k16.row.col.f32.bf16.bf16.f32 "
        "{%0,%1,%2,%3}, {%4,%5,%6,%7}, {%8,%9}, {%0,%1,%2,%3};"
        : "+f"(d[0]), "+f"(d[1]), "+f"(d[2]), "+f"(d[3])
        : "r"(a[0]), "r"(a[1]), "r"(a[2]), "r"(a[3]), "r"(b[0]), "r"(b[1]));
}

// ---------------------------------------------------------------------------
// fp32 -> (hi, lo) bf16 split, vectorized
// ---------------------------------------------------------------------------
__global__ void __launch_bounds__(256)
split_hi_lo(const float* __restrict__ x,
            __nv_bfloat16* __restrict__ hi,
            __nv_bfloat16* __restrict__ lo, int n4)
{
    int i = blockIdx.x * blockDim.x + threadIdx.x;
    if (i >= n4) return;
    float4 v = ((const float4*)x)[i];
    __nv_bfloat16 h0 = __float2bfloat16(v.x);
    __nv_bfloat16 h1 = __float2bfloat16(v.y);
    __nv_bfloat16 h2 = __float2bfloat16(v.z);
    __nv_bfloat16 h3 = __float2bfloat16(v.w);
    __nv_bfloat16 l0 = __float2bfloat16(v.x - __bfloat162float(h0));
    __nv_bfloat16 l1 = __float2bfloat16(v.y - __bfloat162float(h1));
    __nv_bfloat16 l2 = __float2bfloat16(v.z - __bfloat162float(h2));
    __nv_bfloat16 l3 = __float2bfloat16(v.w - __bfloat162float(h3));
    __nv_bfloat162* hp = (__nv_bfloat162*)hi;
    __nv_bfloat162* lp = (__nv_bfloat162*)lo;
    hp[2 * i]     = __nv_bfloat162(h0, h1);
    hp[2 * i + 1] = __nv_bfloat162(h2, h3);
    lp[2 * i]     = __nv_bfloat162(l0, l1);
    lp[2 * i + 1] = __nv_bfloat162(l2, l3);
}

// ---------------------------------------------------------------------------
// HMMA GEMM: C[m,n] = sum_k A[m,k]*W[n,k] + bias[n]
// fp32 via bf16 hi/lo 3-term. CTA tile 128x128, BK=32, 256 thr, warp 32x64.
// Smem rows padded to 40 bf16 (80B) -> conflict-free ldmatrix.
// ---------------------------------------------------------------------------
#define BK       32
#define NK       (DMODEL / BK)            // 32
#define ROWB     80                       // bytes per padded smem row
#define MATB     (128 * ROWB)             // 10240 B per matrix tile
#define STAGEB   (4 * MATB)               // Ahi, Alo, Bhi, Blo
#define SMEM_GEMM (2 * STAGEB)            // 81920 B

__global__ void __launch_bounds__(256, 1)
gemm_hmma(const __nv_bfloat16* __restrict__ Ahi, const __nv_bfloat16* __restrict__ Alo,
          const __nv_bfloat16* __restrict__ Bhi, const __nv_bfloat16* __restrict__ Blo,
          const float* __restrict__ bias, float* __restrict__ C)
{
    extern __shared__ char smem[];
    const uint32_t sb = smem_u32(smem);

    const int tid  = threadIdx.x;
    const int wid  = tid >> 5;
    const int lane = tid & 31;
    const int bn = blockIdx.x * 128;
    const int bm = blockIdx.y * 128;

    const int wm = (wid & 3) * 32;    // warp row base within CTA tile
    const int wn = (wid >> 2) * 64;   // warp col base

    // ldmatrix per-lane addressing pieces
    const int rowA = (lane & 7) + ((lane >> 3) & 1) * 8;  // + kb (lane/16)*16B
    const int kbA  = (lane >> 4) * 16;
    const int rowB = (lane & 7) + (lane >> 4) * 8;
    const int kbB  = ((lane >> 3) & 1) * 16;

    // cp.async chunk mapping: 2048 16B-chunks/stage, 8 per thread
    const __nv_bfloat16* srcs[4] = {
        Ahi + (size_t)bm * DMODEL, Alo + (size_t)bm * DMODEL,
        Bhi + (size_t)bn * DMODEL, Blo + (size_t)bn * DMODEL };

    float acc[2][8][4];
#pragma unroll
    for (int mt = 0; mt < 2; mt++)
#pragma unroll
        for (int nt = 0; nt < 8; nt++)
#pragma unroll
            for (int e = 0; e < 4; e++) acc[mt][nt][e] = 0.0f;

    // ---- stage loader ----
    auto load_stage = [&](int s, int k0) {
        const uint32_t stage = sb + (uint32_t)s * STAGEB;
#pragma unroll
        for (int i = 0; i < 8; i++) {
            const int c   = tid + i * 256;        // 0..2047
            const int mat = c >> 9;               // /512
            const int idx = c & 511;
            const int row = idx >> 2;
            const int seg = idx & 3;
            const __nv_bfloat16* g = srcs[mat] + (size_t)row * DMODEL + k0 + seg * 8;
            const uint32_t d = stage + (uint32_t)mat * MATB + row * ROWB + seg * 16;
            CP_ASYNC16(d, g);
        }
        CP_COMMIT();
    };

    load_stage(0, 0);

    for (int k = 0; k < NK; k++) {
        const int s = k & 1;
        if (k + 1 < NK) { load_stage(s ^ 1, (k + 1) * BK); CP_WAIT(1); }
        else            { CP_WAIT(0); }
        __syncthreads();

        const uint32_t stage = sb + (uint32_t)s * STAGEB;
        const uint32_t sAhi = stage + 0 * MATB;
        const uint32_t sAlo = stage + 1 * MATB;
        const uint32_t sBhi = stage + 2 * MATB;
        const uint32_t sBlo = stage + 3 * MATB;

#pragma unroll
        for (int kh = 0; kh < 2; kh++) {              // two k16 halves of BK=32
            const int khb = kh * 32;                  // byte offset of k-half
            uint32_t ah[2][4], al[2][4];
#pragma unroll
            for (int mt = 0; mt < 2; mt++) {
                const uint32_t ao = (uint32_t)(wm + mt * 16 + rowA) * ROWB + khb + kbA;
                ldsm_x4(ah[mt][0], ah[mt][1], ah[mt][2], ah[mt][3], sAhi + ao);
                ldsm_x4(al[mt][0], al[mt][1], al[mt][2], al[mt][3], sAlo + ao);
            }
            uint32_t bh[4][4], bl[4][4];
#pragma unroll
            for (int np = 0; np < 4; np++) {
                const uint32_t bo = (uint32_t)(wn + np * 16 + rowB) * ROWB + khb + kbB;
                ldsm_x4(bh[np][0], bh[np][1], bh[np][2], bh[np][3], sBhi + bo);
                ldsm_x4(bl[np][0], bl[np][1], bl[np][2], bl[np][3], sBlo + bo);
            }
#pragma unroll
            for (int mt = 0; mt < 2; mt++) {
#pragma unroll
                for (int np = 0; np < 4; np++) {
                    // term hi*hi
                    mma_bf16(acc[mt][2 * np + 0], ah[mt], &bh[np][0]);
                    mma_bf16(acc[mt][2 * np + 1], ah[mt], &bh[np][2]);
                    // term hi*lo
                    mma_bf16(acc[mt][2 * np + 0], ah[mt], &bl[np][0]);
                    mma_bf16(acc[mt][2 * np + 1], ah[mt], &bl[np][2]);
                    // term lo*hi
                    mma_bf16(acc[mt][2 * np + 0], al[mt], &bh[np][0]);
                    mma_bf16(acc[mt][2 * np + 1], al[mt], &bh[np][2]);
                }
            }
        }
        __syncthreads();   // stage s will be overwritten next iteration
    }

    // ---- epilogue: bias + store ----
    const int r0 = lane >> 2;          // 0..7
    const int c0 = (lane & 3) * 2;     // 0,2,4,6
#pragma unroll
    for (int mt = 0; mt < 2; mt++) {
#pragma unroll
        for (int nt = 0; nt < 8; nt++) {
            const int col = bn + wn + nt * 8 + c0;
            const float b0 = bias[col], b1 = bias[col + 1];
            const int rA = bm + wm + mt * 16 + r0;
            float2 v0, v1;
            v0.x = acc[mt][nt][0] + b0; v0.y = acc[mt][nt][1] + b1;
            v1.x = acc[mt][nt][2] + b0; v1.y = acc[mt][nt][3] + b1;
            *(float2*)(C + (size_t)rA * DMODEL + col)       = v0;
            *(float2*)(C + (size_t)(rA + 8) * DMODEL + col) = v1;
        }
    }
}

// ---------------------------------------------------------------------------
// Causal flash attention, fp32 (unchanged — R1-verified)
// ---------------------------------------------------------------------------
#define FA_PAD 68

__global__ void __launch_bounds__(256)
flash_attn(const float* __restrict__ Qg,
           const float* __restrict__ Kg,
           const float* __restrict__ Vg,
           float* __restrict__ Og)
{
    extern __shared__ float sm[];
    float (*Qs)[FA_PAD] = (float(*)[FA_PAD])(sm);
    float (*Ks)[FA_PAD] = (float(*)[FA_PAD])(sm + 64 * FA_PAD);
    float (*Vs)[FA_PAD] = (float(*)[FA_PAD])(sm + 2 * 64 * FA_PAD);
    float (*Ps)[FA_PAD] = (float(*)[FA_PAD])(sm + 3 * 64 * FA_PAD);

    const int tid = threadIdx.x;
    const int tx  = tid & 15;
    const int ty  = tid >> 4;

    const int qi = blockIdx.x;
    const int bh = blockIdx.y;
    const int b  = bh >> 4;
    const int h  = bh & 15;

    const size_t headoff = (size_t)b * SEQ * DMODEL + (size_t)h * HDIM;
    const float* Qbase = Qg + headoff;
    const float* Kbase = Kg + headoff;
    const float* Vbase = Vg + headoff;

    const int qb = qi * 64;

    {
        const int lr = tid >> 4;
        const int lc = (tid & 15) * 4;
#pragma unroll
        for (int r = 0; r < 4; r++) {
            const int row = lr + r * 16;
            float4 v = *(const float4*)(Qbase + (size_t)(qb + row) * DMODEL + lc);
            Qs[lc + 0][row] = v.x; Qs[lc + 1][row] = v.y;
            Qs[lc + 2][row] = v.z; Qs[lc + 3][row] = v.w;
        }
    }

    float o[4][4];
    float m_run[4], l_run[4];
#pragma unroll
    for (int i = 0; i < 4; i++) {
        m_run[i] = -1e30f;
        l_run[i] = 0.0f;
#pragma unroll
        for (int j = 0; j < 4; j++) o[i][j] = 0.0f;
    }

    for (int kt = 0; kt <= qi; kt++) {
        __syncthreads();
        {
            const int lr = tid >> 4;
            const int lc = (tid & 15) * 4;
#pragma unroll
            for (int r = 0; r < 4; r++) {
                const int row = lr + r * 16;
                const size_t goff = (size_t)(kt * 64 + row) * DMODEL + lc;
                float4 kv = *(const float4*)(Kbase + goff);
                Ks[lc + 0][row] = kv.x; Ks[lc + 1][row] = kv.y;
                Ks[lc + 2][row] = kv.z; Ks[lc + 3][row] = kv.w;
                float4 vv = *(const float4*)(Vbase + goff);
                *(float4*)&Vs[row][lc] = vv;
            }
        }
        __syncthreads();

        float s[4][4];
#pragma unroll
        for (int i = 0; i < 4; i++)
#pragma unroll
            for (int j = 0; j < 4; j++) s[i][j] = 0.0f;

#pragma unroll 8
        for (int d = 0; d < 64; d++) {
            float4 aq = *(const float4*)&Qs[d][ty * 4];
            float4 bk = *(const float4*)&Ks[d][tx * 4];
            float a[4] = {aq.x, aq.y, aq.z, aq.w};
            float bb[4] = {bk.x, bk.y, bk.z, bk.w};
#pragma unroll
            for (int i = 0; i < 4; i++)
#pragma unroll
                for (int j = 0; j < 4; j++)
                    s[i][j] = fmaf(a[i], bb[j], s[i][j]);
        }

        const bool diag = (kt == qi);
#pragma unroll
        for (int i = 0; i < 4; i++) {
            const int qrow = qb + ty * 4 + i;
#pragma unroll
            for (int j = 0; j < 4; j++) {
                s[i][j] *= SCALE_QK;
                if (diag) {
                    const int kcol = kt * 64 + tx * 4 + j;
                    if (kcol > qrow) s[i][j] = -1e30f;
                }
            }
        }

#pragma unroll
        for (int i = 0; i < 4; i++) {
            float rm = fmaxf(fmaxf(s[i][0], s[i][1]), fmaxf(s[i][2], s[i][3]));
#pragma unroll
            for (int off = 8; off > 0; off >>= 1)
                rm = fmaxf(rm, __shfl_xor_sync(0xffffffffu, rm, off));

            const float mnew  = fmaxf(m_run[i], rm);
            const float alpha = __expf(m_run[i] - mnew);

            float p0 = __expf(s[i][0] - mnew);
            float p1 = __expf(s[i][1] - mnew);
            float p2 = __expf(s[i][2] - mnew);
            float p3 = __expf(s[i][3] - mnew);

            float rs = p0 + p1 + p2 + p3;
#pragma unroll
            for (int off = 8; off > 0; off >>= 1)
                rs += __shfl_xor_sync(0xffffffffu, rs, off);

            l_run[i] = l_run[i] * alpha + rs;
            m_run[i] = mnew;
#pragma unroll
            for (int j = 0; j < 4; j++) o[i][j] *= alpha;

            const int qloc = ty * 4 + i;
            Ps[tx * 4 + 0][qloc] = p0;
            Ps[tx * 4 + 1][qloc] = p1;
            Ps[tx * 4 + 2][qloc] = p2;
            Ps[tx * 4 + 3][qloc] = p3;
        }
        __syncthreads();

#pragma unroll 8
        for (int kk = 0; kk < 64; kk++) {
            float4 ap = *(const float4*)&Ps[kk][ty * 4];
            float4 bv = *(const float4*)&Vs[kk][tx * 4];
            float a[4] = {ap.x, ap.y, ap.z, ap.w};
            float bb[4] = {bv.x, bv.y, bv.z, bv.w};
#pragma unroll
            for (int i = 0; i < 4; i++)
#pragma unroll
                for (int j = 0; j < 4; j++)
                    o[i][j] = fmaf(a[i], bb[j], o[i][j]);
        }
    }

#pragma unroll
    for (int i = 0; i < 4; i++) {
        const float inv = 1.0f / l_run[i];
        const int qrow = qb + ty * 4 + i;
        float* orow = Og + (size_t)b * SEQ * DMODEL + (size_t)qrow * DMODEL
                    + (size_t)h * HDIM + tx * 4;
        float4 ov;
        ov.x = o[i][0] * inv; ov.y = o[i][1] * inv;
        ov.z = o[i][2] * inv; ov.w = o[i][3] * inv;
        *(float4*)orow = ov;
    }
}

// ---------------------------------------------------------------------------
// Launch
// ---------------------------------------------------------------------------
extern "C" void kernel_launch(void* const* d_in, const int* in_sizes, int n_in,
                              void* d_out, int out_size)
{
    (void)in_sizes; (void)n_in; (void)out_size;
    const float* query = (const float*)d_in[0];
    const float* key   = (const float*)d_in[1];
    const float* value = (const float*)d_in[2];
    // d_in[3] = mask (tril) — causal hardcoded
    const float* wq = (const float*)d_in[4];
    const float* bq = (const float*)d_in[5];
    const float* wk = (const float*)d_in[6];
    const float* bk = (const float*)d_in[7];
    const float* wv = (const float*)d_in[8];
    const float* bv = (const float*)d_in[9];
    const float* wo = (const float*)d_in[10];
    const float* bo = (const float*)d_in[11];
    float* out = (float*)d_out;

    float *gQ, *gK, *gV, *gC;
    __nv_bfloat16 *gAhi, *gAlo, *gWhi, *gWlo;
    cudaGetSymbolAddress((void**)&gQ, g_Q);
    cudaGetSymbolAddress((void**)&gK, g_K);
    cudaGetSymbolAddress((void**)&gV, g_V);
    cudaGetSymbolAddress((void**)&gC, g_CTX);
    cudaGetSymbolAddress((void**)&gAhi, g_Ahi);
    cudaGetSymbolAddress((void**)&gAlo, g_Alo);
    cudaGetSymbolAddress((void**)&gWhi, g_Whi);
    cudaGetSymbolAddress((void**)&gWlo, g_Wlo);

    const int fa_smem = 4 * 64 * FA_PAD * (int)sizeof(float);
    cudaFuncSetAttribute(gemm_hmma,
                         cudaFuncAttributeMaxDynamicSharedMemorySize, SMEM_GEMM);
    cudaFuncSetAttribute(flash_attn,
                         cudaFuncAttributeMaxDynamicSharedMemorySize, fa_smem);

    const int nA4 = MROWS * DMODEL / 4;
    const int nW4 = DMODEL * DMODEL / 4;
    const dim3 ggrid(DMODEL / 128, MROWS / 128);   // (8, 64)

    // Q projection
    split_hi_lo<<<nA4 / 256, 256>>>(query, gAhi, gAlo, nA4);
    split_hi_lo<<<nW4 / 256, 256>>>(wq, gWhi, gWlo, nW4);
    gemm_hmma<<<ggrid, 256, SMEM_GEMM>>>(gAhi, gAlo, gWhi, gWlo, bq, gQ);
    // K projection
    split_hi_lo<<<nA4 / 256, 256>>>(key, gAhi, gAlo, nA4);
    split_hi_lo<<<nW4 / 256, 256>>>(wk, gWhi, gWlo, nW4);
    gemm_hmma<<<ggrid, 256, SMEM_GEMM>>>(gAhi, gAlo, gWhi, gWlo, bk, gK);
    // V projection
    split_hi_lo<<<nA4 / 256, 256>>>(value, gAhi, gAlo, nA4);
    split_hi_lo<<<nW4 / 256, 256>>>(wv, gWhi, gWlo, nW4);
    gemm_hmma<<<ggrid, 256, SMEM_GEMM>>>(gAhi, gAlo, gWhi, gWlo, bv, gV);

    // attention
    flash_attn<<<dim3(SEQ / 64, BATCH * NHEAD), 256, fa_smem>>>(gQ, gK, gV, gC);

    // O projection
    split_hi_lo<<<nA4 / 256, 256>>>(gC, gAhi, gAlo, nA4);
    split_hi_lo<<<nW4 / 256, 256>>>(wo, gWhi, gWlo, nW4);
    gemm_hmma<<<ggrid, 256, SMEM_GEMM>>>(gAhi, gAlo, gWhi, gWlo, bo, out);
}